// round 10
// baseline (speedup 1.0000x reference)
#include <cuda_runtime.h>
#include <cstdint>

#define SEQ   4096
#define BATCH 64
#define INP   64
#define HID   256
#define G3    768
#define BG    16          // batch columns (4 batches each) = clusters
#define HG    8           // hidden groups (32 units each) = cluster size
#define NCTA  (BG*HG)     // 128 scan CTAs

// Scratch (static device allocations are the sanctioned workaround)
__device__ float d_xg[(size_t)SEQ * G3 * BATCH];     // [s][g][b]
__device__ float d_fcp[(size_t)NCTA * SEQ * 4];      // [(bg*8+hg)][t][b4]

__device__ __forceinline__ void fma2(unsigned long long& acc,
                                     unsigned long long a,
                                     unsigned long long b) {
    asm("fma.rn.f32x2 %0, %1, %2, %0;" : "+l"(acc) : "l"(a), "l"(b));
}
__device__ __forceinline__ unsigned long long pk(float a, float b) {
    unsigned long long r;
    asm("mov.b64 %0, {%1, %2};" : "=l"(r) : "f"(a), "f"(b));
    return r;
}
__device__ __forceinline__ float2 unpk(unsigned long long v) {
    float lo, hi;
    asm("mov.b64 {%0, %1}, %2;" : "=f"(lo), "=f"(hi) : "l"(v));
    return make_float2(lo, hi);
}
__device__ __forceinline__ uint32_t smem_u32(const void* p) {
    uint32_t a;
    asm("{ .reg .u64 t; cvta.to.shared.u64 t, %1; cvt.u32.u64 %0, t; }"
        : "=r"(a) : "l"(p));
    return a;
}
__device__ __forceinline__ uint32_t mapa_u32(uint32_t smem_addr, uint32_t rank) {
    uint32_t r;
    asm("mapa.shared::cluster.u32 %0, %1, %2;" : "=r"(r) : "r"(smem_addr), "r"(rank));
    return r;
}
#define CLUSTER_SYNC() do { \
    asm volatile("barrier.cluster.arrive.aligned;" ::: "memory"); \
    asm volatile("barrier.cluster.wait.aligned;"   ::: "memory"); \
} while (0)

// ---------------------------------------------------------------------------
// Kernel A: xg[s][g][b] = sum_i x[s][b][i] * w_ih[g][i] + b_ih[g]
// ---------------------------------------------------------------------------
__global__ void __launch_bounds__(256) xg_kernel(const float* __restrict__ x,
                                                 const float* __restrict__ w_ih,
                                                 const float* __restrict__ b_ih) {
    __shared__ float xs[INP][BATCH + 1];
    __shared__ float ws[64][INP];
    const int s   = blockIdx.x;
    const int g0  = blockIdx.y * 64;
    const int tid = threadIdx.x;

    const float* xsrc = x + (size_t)s * BATCH * INP;
    for (int idx = tid; idx < BATCH * INP; idx += 256) {
        int b = idx >> 6, i = idx & 63;
        xs[i][b] = xsrc[idx];
    }
    const float* wsrc = w_ih + (size_t)g0 * INP;
    for (int idx = tid; idx < 64 * INP; idx += 256)
        ws[idx >> 6][idx & 63] = wsrc[idx];
    __syncthreads();

    const int b  = tid & 63;
    const int gg = tid >> 6;
    float xr[INP];
#pragma unroll
    for (int i = 0; i < INP; i++) xr[i] = xs[i][b];

    float acc[16];
#pragma unroll
    for (int u = 0; u < 16; u++) acc[u] = 0.0f;
    const int gb = gg * 16;
#pragma unroll
    for (int i4 = 0; i4 < INP / 4; i4++) {
#pragma unroll
        for (int u = 0; u < 16; u++) {
            float4 w4 = *(const float4*)&ws[gb + u][i4 * 4];
            acc[u] += w4.x * xr[i4 * 4 + 0];
            acc[u] += w4.y * xr[i4 * 4 + 1];
            acc[u] += w4.z * xr[i4 * 4 + 2];
            acc[u] += w4.w * xr[i4 * 4 + 3];
        }
    }
    float* dst = d_xg + ((size_t)s * G3 + g0) * BATCH;
#pragma unroll
    for (int u = 0; u < 16; u++) {
        int gl = gb + u;
        __stcs(&dst[(size_t)gl * BATCH + b], acc[u] + b_ih[g0 + gl]);
    }
}

// ---------------------------------------------------------------------------
// Kernel B: persistent GRU scan, DSMEM epoch-mailbox (no in-loop barriers).
// Cluster of 8 CTAs = one batch column (4 batches). CTA rank hg: 32 units,
// weights register-resident. Producers push (epoch<<32|f32) u64 mail into all
// 8 peers' smem (st.shared::cluster, parity double buffer). Warp w consumes
// producer w's mail from LOCAL smem (volatile poll, ~29cyc quantization),
// stages, strip-MACs immediately (ready-order). Combine via smem + 1 bar.
// ---------------------------------------------------------------------------
__global__ void __launch_bounds__(256, 1) __cluster_dims__(HG, 1, 1)
scan_kernel(const float* __restrict__ w_hh,
            const float* __restrict__ b_hh,
            const float* __restrict__ fc_w) {
    __shared__ __align__(16) unsigned long long mail[2][HG][32][4]; // 16 KB
    __shared__ float hsm[HG][4][32];       // [warp][b_local][k_local]
    __shared__ float red[HG][3][128];      // [warp][gate][j*4+b]
    __shared__ float fcred[4][32];         // [b_local][j]

    const int c    = blockIdx.x;
    const int bg   = c >> 3;               // cluster id (batch column)
    const int hg   = c & 7;                // rank in cluster = hidden group
    const int tid  = threadIdx.x;
    const int w    = tid >> 5;             // warp = producer index = k strip
    const int lane = tid & 31;

    // Zero own mailbox (both parities) before any peer can write epoch-1 mail
    {
        unsigned long long* mb = &mail[0][0][0][0];
        for (int i = tid; i < 2 * HG * 32 * 4; i += 256) mb[i] = 0ull;
    }

    // Weights: unit u = hg*32+lane, k in [w*32, w*32+32), k-paired as float2
    unsigned long long w2[3][16];
#pragma unroll
    for (int g = 0; g < 3; g++)
#pragma unroll
        for (int q = 0; q < 8; q++) {
            const float4 v = *(const float4*)&w_hh[
                ((size_t)(g * HID + hg * 32 + lane)) * HID + w * 32 + q * 4];
            w2[g][q * 2 + 0] = pk(v.x, v.y);
            w2[g][q * 2 + 1] = pk(v.z, v.w);
        }

    // Pointwise mapping (tid < 128): unit pj, batch pb
    const int pj = tid >> 2;
    const int pb = tid & 3;
    const int u  = hg * 32 + pj;
    const float bh_r = b_hh[u];
    const float bh_z = b_hh[HID + u];
    const float bh_n = b_hh[2 * HID + u];
    const float fw   = fc_w[u];

    // Remote mail addresses: slot [0][hg][pj][pb] in each peer's smem
    uint32_t rbase[HG];
    if (tid < 128) {
        const uint32_t local = smem_u32(&mail[0][hg][pj][pb]);
#pragma unroll
        for (int r = 0; r < HG; r++) rbase[r] = mapa_u32(local, (uint32_t)r);
    }
    // Local poll address: warp w's producer block, lane's unit (parity 0)
    const uint32_t pollb = smem_u32(&mail[0][w][lane][0]);

    __syncthreads();
    CLUSTER_SYNC();                        // all mailboxes zeroed (startup only)

    float h_prev = 0.0f;
    for (int t = 0; t < SEQ; t++) {
        // Prefetch input-side gates (overlaps poll + MAC)
        float xrv = 0.f, xzv = 0.f, xnv = 0.f;
        if (tid < 128) {
            const size_t base = ((size_t)t * G3 + u) * BATCH + (bg * 4 + pb);
            xrv = __ldcs(&d_xg[base]);
            xzv = __ldcs(&d_xg[base + (size_t)HID * BATCH]);
            xnv = __ldcs(&d_xg[base + (size_t)2 * HID * BATCH]);
        }

        unsigned long long acc[3][4];
#pragma unroll
        for (int g = 0; g < 3; g++)
#pragma unroll
            for (int b = 0; b < 4; b++) acc[g][b] = 0ull;

        if (t > 0) {
            // Poll producer w's mail in LOCAL smem (epoch t, parity (t-1)&1)
            const unsigned long long tt = (unsigned long long)t;
            const uint32_t mp = pollb + (uint32_t)(((t - 1) & 1) * 8192);
            unsigned long long m0, m1, m2, m3;
            bool ok;
            do {
                asm volatile("ld.volatile.shared.v2.u64 {%0,%1}, [%2];"
                             : "=l"(m0), "=l"(m1) : "r"(mp));
                asm volatile("ld.volatile.shared.v2.u64 {%0,%1}, [%2];"
                             : "=l"(m2), "=l"(m3) : "r"(mp + 16));
                ok = __all_sync(0xFFFFFFFFu,
                                ((m0 >> 32) == tt) & ((m1 >> 32) == tt) &
                                ((m2 >> 32) == tt) & ((m3 >> 32) == tt));
            } while (!ok);
            hsm[w][0][lane] = __uint_as_float((unsigned)m0);
            hsm[w][1][lane] = __uint_as_float((unsigned)m1);
            hsm[w][2][lane] = __uint_as_float((unsigned)m2);
            hsm[w][3][lane] = __uint_as_float((unsigned)m3);
            __syncwarp();                  // warp-local staging only

            // Strip MAC: 192 fma2, hsm loads broadcast within warp
#pragma unroll
            for (int b = 0; b < 4; b++) {
#pragma unroll
                for (int q = 0; q < 8; q++) {
                    const ulonglong2 hh = *(const ulonglong2*)&hsm[w][b][q * 4];
#pragma unroll
                    for (int g = 0; g < 3; g++) {
                        fma2(acc[g][b], w2[g][q * 2 + 0], hh.x);
                        fma2(acc[g][b], w2[g][q * 2 + 1], hh.y);
                    }
                }
            }
        }

        // Per-warp partials: lane = unit, 4 batches packed per gate
#pragma unroll
        for (int g = 0; g < 3; g++) {
            const float2 a0 = unpk(acc[g][0]);
            const float2 a1 = unpk(acc[g][1]);
            const float2 a2 = unpk(acc[g][2]);
            const float2 a3 = unpk(acc[g][3]);
            float4 v = make_float4(a0.x + a0.y, a1.x + a1.y,
                                   a2.x + a2.y, a3.x + a3.y);
            *(float4*)&red[w][g][lane * 4] = v;
        }
        __syncthreads();                   // all warps' partials visible

        if (tid < 128) {
            float sr = 0.f, sz = 0.f, sn = 0.f;
            const int o = pj * 4 + pb;
#pragma unroll
            for (int ww = 0; ww < HG; ww++) {
                sr += red[ww][0][o];
                sz += red[ww][1][o];
                sn += red[ww][2][o];
            }
            // torch GRU: n = tanh(xn + r*(hn + bhh_n))
            const float rg_ = 1.0f / (1.0f + __expf(-(xrv + sr + bh_r)));
            const float zg_ = 1.0f / (1.0f + __expf(-(xzv + sz + bh_z)));
            const float ng_ = tanhf(xnv + rg_ * (sn + bh_n));
            const float hnew = (1.0f - zg_) * ng_ + zg_ * h_prev;
            h_prev = hnew;
            // Push mail to all 8 peers immediately: epoch t+1, parity t&1
            const unsigned long long mmail =
                ((unsigned long long)(t + 1) << 32) |
                (unsigned long long)__float_as_uint(hnew);
            const uint32_t poff = (uint32_t)((t & 1) * 8192);
#pragma unroll
            for (int r = 0; r < HG; r++)
                asm volatile("st.shared::cluster.u64 [%0], %1;"
                             :: "r"(rbase[r] + poff), "l"(mmail) : "memory");
            fcred[pb][pj] = fw * hnew;
        }
        __syncthreads();                   // fcred ready; red reusable

        if (tid < 4) {                     // fc partial (off critical path)
            float fs = 0.0f;
#pragma unroll
            for (int j = 0; j < 32; j++) fs += fcred[tid][j];
            d_fcp[((size_t)(bg * HG + hg) * SEQ + t) * 4 + tid] = fs;
        }
    }
    CLUSTER_SYNC();                        // drain in-flight peer stores
}

// ---------------------------------------------------------------------------
// Kernel C: out[s][b] = fc_b + sum_hg fcp
// ---------------------------------------------------------------------------
__global__ void __launch_bounds__(512) final_kernel(const float* __restrict__ fc_b,
                                                    float* __restrict__ out) {
    const int idx = blockIdx.x * 512 + threadIdx.x;
    if (idx >= SEQ * BATCH) return;
    const int s  = idx >> 6;
    const int b6 = idx & 63;
    const int bg = b6 >> 2;
    const int bl = b6 & 3;
    float sum = fc_b[0];
#pragma unroll
    for (int hg = 0; hg < HG; hg++)
        sum += d_fcp[((size_t)(bg * HG + hg) * SEQ + s) * 4 + bl];
    out[idx] = sum;
}

extern "C" void kernel_launch(void* const* d_in, const int* in_sizes, int n_in,
                              void* d_out, int out_size) {
    const float* x    = (const float*)d_in[0];
    const float* w_ih = (const float*)d_in[1];
    const float* w_hh = (const float*)d_in[2];
    const float* b_ih = (const float*)d_in[3];
    const float* b_hh = (const float*)d_in[4];
    const float* fc_w = (const float*)d_in[5];
    const float* fc_b = (const float*)d_in[6];
    float* out = (float*)d_out;

    dim3 ga(SEQ, G3 / 64);
    xg_kernel<<<ga, 256>>>(x, w_ih, b_ih);                 // input projections
    scan_kernel<<<NCTA, 256>>>(w_hh, b_hh, fc_w);          // DSMEM mailbox scan
    final_kernel<<<(SEQ * BATCH + 511) / 512, 512>>>(fc_b, out);
}

// round 13
// speedup vs baseline: 1.4387x; 1.4387x over previous
#include <cuda_runtime.h>
#include <cstdint>

#define SEQ   4096
#define BATCH 64
#define INP   64
#define HID   256
#define G3    768
#define BG    16          // batch columns (4 batches each)
#define HG    8           // hidden groups (32 units each) = warps/CTA
#define NCTA  (BG*HG)     // 128 scan CTAs, occupancy 1

// Scratch (static device allocations are the sanctioned workaround)
__device__ float d_xg[(size_t)SEQ * G3 * BATCH];             // [s][g][b]
__device__ unsigned long long d_hmail[2 * BG * HG * 32 * 4]; // [par][bg][p][j][b]
__device__ float d_fcp[(size_t)NCTA * SEQ * 16];             // [bg*8+hg][t][warp][b4]

__device__ __forceinline__ void fma2(unsigned long long& acc,
                                     unsigned long long a,
                                     unsigned long long b) {
    asm("fma.rn.f32x2 %0, %1, %2, %0;" : "+l"(acc) : "l"(a), "l"(b));
}
__device__ __forceinline__ unsigned long long pk(float a, float b) {
    unsigned long long r;
    asm("mov.b64 %0, {%1, %2};" : "=l"(r) : "f"(a), "f"(b));
    return r;
}
__device__ __forceinline__ float2 unpk(unsigned long long v) {
    float lo, hi;
    asm("mov.b64 {%0, %1}, %2;" : "=f"(lo), "=f"(hi) : "l"(v));
    return make_float2(lo, hi);
}

// ---------------------------------------------------------------------------
// Kernel A: xg[s][g][b] = sum_i x[s][b][i] * w_ih[g][i] + b_ih[g]
// ---------------------------------------------------------------------------
__global__ void __launch_bounds__(256) xg_kernel(const float* __restrict__ x,
                                                 const float* __restrict__ w_ih,
                                                 const float* __restrict__ b_ih) {
    __shared__ float xs[INP][BATCH + 1];
    __shared__ float ws[64][INP];
    const int s   = blockIdx.x;
    const int g0  = blockIdx.y * 64;
    const int tid = threadIdx.x;

    const float* xsrc = x + (size_t)s * BATCH * INP;
    for (int idx = tid; idx < BATCH * INP; idx += 256) {
        int b = idx >> 6, i = idx & 63;
        xs[i][b] = xsrc[idx];
    }
    const float* wsrc = w_ih + (size_t)g0 * INP;
    for (int idx = tid; idx < 64 * INP; idx += 256)
        ws[idx >> 6][idx & 63] = wsrc[idx];
    __syncthreads();

    const int b  = tid & 63;
    const int gg = tid >> 6;
    float xr[INP];
#pragma unroll
    for (int i = 0; i < INP; i++) xr[i] = xs[i][b];

    float acc[16];
#pragma unroll
    for (int u = 0; u < 16; u++) acc[u] = 0.0f;
    const int gb = gg * 16;
#pragma unroll
    for (int i4 = 0; i4 < INP / 4; i4++) {
#pragma unroll
        for (int u = 0; u < 16; u++) {
            float4 w4 = *(const float4*)&ws[gb + u][i4 * 4];
            acc[u] += w4.x * xr[i4 * 4 + 0];
            acc[u] += w4.y * xr[i4 * 4 + 1];
            acc[u] += w4.z * xr[i4 * 4 + 2];
            acc[u] += w4.w * xr[i4 * 4 + 3];
        }
    }
    float* dst = d_xg + ((size_t)s * G3 + g0) * BATCH;
#pragma unroll
    for (int u = 0; u < 16; u++) {
        int gl = gb + u;
        __stcs(&dst[(size_t)gl * BATCH + b], acc[u] + b_ih[g0 + gl]);
    }
}

// ---------------------------------------------------------------------------
// Kernel B: persistent GRU scan, warp-per-producer ready-order consumption,
// ONE __syncthreads per step (parity-double-buffered partials; WAR closed
// transitively through the mail dependency chain), in-warp fc reduction.
// Exact activations. FIX vs R11/R12: fc partials stored at cc = bg*HG+hg
// (blockIdx.x = hg*16+bg — the reader indexes [bg*8+hg]; mismatch was the
// deterministic rel_err=1.23 in both failing rounds).
// ---------------------------------------------------------------------------
__global__ void __launch_bounds__(256, 1) scan_kernel(const float* __restrict__ w_hh,
                                                      const float* __restrict__ b_hh,
                                                      const float* __restrict__ fc_w) {
    __shared__ float hsm[HG][4][32];       // [warp][b_local][k_local]
    __shared__ float red[2][HG][3][128];   // [parity][warp][gate][j*4+b]

    const int c    = blockIdx.x;
    const int bg   = c & (BG - 1);
    const int hg   = c >> 4;
    const int cc   = bg * HG + hg;         // canonical CTA index for d_fcp
    const int tid  = threadIdx.x;
    const int w    = tid >> 5;             // warp = producer index = k strip
    const int lane = tid & 31;

    // Weights: unit u = hg*32+lane, k in [w*32, w*32+32), k-paired as float2
    unsigned long long w2[3][16];
#pragma unroll
    for (int g = 0; g < 3; g++)
#pragma unroll
        for (int q = 0; q < 8; q++) {
            const float4 v = *(const float4*)&w_hh[
                ((size_t)(g * HID + hg * 32 + lane)) * HID + w * 32 + q * 4];
            w2[g][q * 2 + 0] = pk(v.x, v.y);
            w2[g][q * 2 + 1] = pk(v.z, v.w);
        }

    // Pointwise mapping (tid < 128): unit pj, batch pb
    const int pj = tid >> 2;
    const int pb = tid & 3;
    const int u  = hg * 32 + pj;
    const float bh_r = b_hh[u];
    const float bh_z = b_hh[HID + u];
    const float bh_n = b_hh[2 * HID + u];
    const float fw   = fc_w[u];

    float h_prev = 0.0f;
    __syncthreads();

    for (int t = 0; t < SEQ; t++) {
        // Prefetch input-side gates (overlaps poll + MAC)
        float xrv = 0.f, xzv = 0.f, xnv = 0.f;
        if (tid < 128) {
            const size_t base = ((size_t)t * G3 + u) * BATCH + (bg * 4 + pb);
            xrv = __ldcs(&d_xg[base]);
            xzv = __ldcs(&d_xg[base + (size_t)HID * BATCH]);
            xnv = __ldcs(&d_xg[base + (size_t)2 * HID * BATCH]);
        }

        unsigned long long acc[3][4];      // [gate][b], f32x2 over (k0,k1)
#pragma unroll
        for (int g = 0; g < 3; g++)
#pragma unroll
            for (int b = 0; b < 4; b++) acc[g][b] = 0ull;

        if (t > 0) {
            // Warp w polls ONLY producer w's mail (epoch t, parity (t-1)&1)
            const unsigned long long tt = (unsigned long long)t;
            const unsigned long long* mp = &d_hmail[
                ((size_t)(((t - 1) & 1) * BG + bg) * HG + w) * 128 + lane * 4];
            unsigned long long m0, m1, m2, m3;
            bool ok;
            do {
                asm volatile("ld.volatile.global.v2.u64 {%0,%1}, [%2];"
                             : "=l"(m0), "=l"(m1) : "l"(mp));
                asm volatile("ld.volatile.global.v2.u64 {%0,%1}, [%2];"
                             : "=l"(m2), "=l"(m3) : "l"(mp + 2));
                ok = __all_sync(0xFFFFFFFFu,
                                ((m0 >> 32) == tt) & ((m1 >> 32) == tt) &
                                ((m2 >> 32) == tt) & ((m3 >> 32) == tt));
            } while (!ok);
            hsm[w][0][lane] = __uint_as_float((unsigned)m0);
            hsm[w][1][lane] = __uint_as_float((unsigned)m1);
            hsm[w][2][lane] = __uint_as_float((unsigned)m2);
            hsm[w][3][lane] = __uint_as_float((unsigned)m3);
            __syncwarp();                  // warp-local staging only

            // Strip MAC: 192 fma2, hsm loads broadcast (same addr all lanes)
#pragma unroll
            for (int b = 0; b < 4; b++) {
#pragma unroll
                for (int q = 0; q < 8; q++) {
                    const ulonglong2 hh = *(const ulonglong2*)&hsm[w][b][q * 4];
#pragma unroll
                    for (int g = 0; g < 3; g++) {
                        fma2(acc[g][b], w2[g][q * 2 + 0], hh.x);
                        fma2(acc[g][b], w2[g][q * 2 + 1], hh.y);
                    }
                }
            }
        }

        // Per-warp partials into parity buffer: lane = unit, 4 batches/gate
        const int par = t & 1;
#pragma unroll
        for (int g = 0; g < 3; g++) {
            const float2 a0 = unpk(acc[g][0]);
            const float2 a1 = unpk(acc[g][1]);
            const float2 a2 = unpk(acc[g][2]);
            const float2 a3 = unpk(acc[g][3]);
            float4 v = make_float4(a0.x + a0.y, a1.x + a1.y,
                                   a2.x + a2.y, a3.x + a3.y);
            *(float4*)&red[par][w][g][lane * 4] = v;
        }
        __syncthreads();                   // the ONLY barrier per step

        if (tid < 128) {
            float sr = 0.f, sz = 0.f, sn = 0.f;
            const int o = pj * 4 + pb;
#pragma unroll
            for (int ww = 0; ww < HG; ww++) {
                sr += red[par][ww][0][o];
                sz += red[par][ww][1][o];
                sn += red[par][ww][2][o];
            }
            // torch GRU: n = tanh(xn + r*(hn + bhh_n)), exact activations
            const float rg_ = 1.0f / (1.0f + __expf(-(xrv + sr + bh_r)));
            const float zg_ = 1.0f / (1.0f + __expf(-(xzv + sz + bh_z)));
            const float ng_ = tanhf(xnv + rg_ * (sn + bh_n));
            const float hnew = fmaf(zg_, h_prev - ng_, ng_);
            h_prev = hnew;
            // Publish mail immediately: epoch t+1 | value, parity t&1
            const unsigned long long mail =
                ((unsigned long long)(t + 1) << 32) |
                (unsigned long long)__float_as_uint(hnew);
            unsigned long long* maddr = &d_hmail[
                ((size_t)(par * BG + bg) * HG + hg) * 128 + pj * 4 + pb];
            asm volatile("st.relaxed.gpu.global.u64 [%0], %1;"
                         :: "l"(maddr), "l"(mail) : "memory");

            // fc partial: butterfly over pj (lane bits 2..4) within the warp
            float fs = fw * hnew;
            fs += __shfl_xor_sync(0xFFFFFFFFu, fs, 4);
            fs += __shfl_xor_sync(0xFFFFFFFFu, fs, 8);
            fs += __shfl_xor_sync(0xFFFFFFFFu, fs, 16);
            if (lane < 4)                  // lane == pb here
                d_fcp[(((size_t)cc * SEQ + t) * 4 + w) * 4 + lane] = fs;
        }
        // no second barrier: red is parity-double-buffered (WAR closed by
        // the publish(t+1) -> poll(t+1) -> ... dependency chain)
    }
}

// ---------------------------------------------------------------------------
// Kernel C: out[s][b] = fc_b + sum over 8 hg x 4 warp partials.
// Also re-zeroes the mailbox (prevents stale-epoch collision on replay).
// ---------------------------------------------------------------------------
__global__ void __launch_bounds__(512) final_kernel(const float* __restrict__ fc_b,
                                                    float* __restrict__ out) {
    const int idx = blockIdx.x * 512 + threadIdx.x;
    if (idx < 2 * BG * HG * 32 * 4)                  // 32768 u64 mail words
        d_hmail[idx] = 0ull;
    if (idx >= SEQ * BATCH) return;
    const int s  = idx >> 6;
    const int b6 = idx & 63;
    const int bg = b6 >> 2;
    const int bl = b6 & 3;
    float sum = fc_b[0];
#pragma unroll
    for (int hg = 0; hg < HG; hg++) {
        const size_t base = (((size_t)(bg * HG + hg) * SEQ + s) * 4) * 4 + bl;
#pragma unroll
        for (int w = 0; w < 4; w++)
            sum += d_fcp[base + w * 4];
    }
    out[idx] = sum;
}

extern "C" void kernel_launch(void* const* d_in, const int* in_sizes, int n_in,
                              void* d_out, int out_size) {
    const float* x    = (const float*)d_in[0];
    const float* w_ih = (const float*)d_in[1];
    const float* w_hh = (const float*)d_in[2];
    const float* b_ih = (const float*)d_in[3];
    const float* b_hh = (const float*)d_in[4];
    const float* fc_w = (const float*)d_in[5];
    const float* fc_b = (const float*)d_in[6];
    float* out = (float*)d_out;

    dim3 ga(SEQ, G3 / 64);
    xg_kernel<<<ga, 256>>>(x, w_ih, b_ih);                 // input projections
    scan_kernel<<<NCTA, 256>>>(w_hh, b_hh, fc_w);          // ready-order scan
    final_kernel<<<(SEQ * BATCH + 511) / 512, 512>>>(fc_b, out);
}

// round 14
// speedup vs baseline: 1.4818x; 1.0299x over previous
#include <cuda_runtime.h>
#include <cstdint>

#define SEQ   4096
#define BATCH 64
#define INP   64
#define HID   256
#define G3    768
#define BG    16          // batch columns (4 batches each)
#define HG    8           // hidden groups (32 units each) = warps/CTA
#define NCTA  (BG*HG)     // 128 scan CTAs, occupancy 1

// Scratch (static device allocations are the sanctioned workaround)
__device__ unsigned long long d_hmail[2 * BG * HG * 32 * 4]; // [par][bg][p][j][b]
__device__ float d_fcp[(size_t)NCTA * SEQ * 4];              // [bg*8+hg][t][b4]

__device__ __forceinline__ void fma2(unsigned long long& acc,
                                     unsigned long long a,
                                     unsigned long long b) {
    asm("fma.rn.f32x2 %0, %1, %2, %0;" : "+l"(acc) : "l"(a), "l"(b));
}
__device__ __forceinline__ unsigned long long pk(float a, float b) {
    unsigned long long r;
    asm("mov.b64 %0, {%1, %2};" : "=l"(r) : "f"(a), "f"(b));
    return r;
}
__device__ __forceinline__ float2 unpk(unsigned long long v) {
    float lo, hi;
    asm("mov.b64 {%0, %1}, %2;" : "=f"(lo), "=f"(hi) : "l"(v));
    return make_float2(lo, hi);
}

// ---------------------------------------------------------------------------
// Kernel B: persistent GRU scan with FUSED input projection (no xg kernel).
// CTA (bg,hg): 4 batches x 32 hidden units. Warp w = producer w's k-strip
// [32w,32w+32) AND x-input strip [8w,8w+8). Four gate accumulators
// {r, z, n_hidden, n_x} because torch's r gates only the hidden n term.
// Warp-per-producer ready-order mail consumption (R9 structure, 2 barriers).
// ---------------------------------------------------------------------------
__global__ void __launch_bounds__(256, 1) scan_kernel(const float* __restrict__ x,
                                                      const float* __restrict__ w_ih,
                                                      const float* __restrict__ w_hh,
                                                      const float* __restrict__ b_ih,
                                                      const float* __restrict__ b_hh,
                                                      const float* __restrict__ fc_w) {
    __shared__ float hsm[HG][4][32];       // [warp][b_local][k_local]
    __shared__ float red[HG][4][128];      // [warp][gate][j*4+b]
    __shared__ float fcred[4][32];         // [b_local][j]
    __shared__ float xsm[2][4][INP];       // [parity][b_local][i]

    const int c    = blockIdx.x;
    const int bg   = c & (BG - 1);
    const int hg   = c >> 4;
    const int cc   = bg * HG + hg;         // canonical CTA index for d_fcp
    const int tid  = threadIdx.x;
    const int w    = tid >> 5;             // warp = producer index = strips
    const int lane = tid & 31;

    // Hidden weights: unit u = hg*32+lane, k in [32w,32w+32), k-paired f32x2
    unsigned long long w2[3][16];
#pragma unroll
    for (int g = 0; g < 3; g++)
#pragma unroll
        for (int q = 0; q < 8; q++) {
            const float4 v = *(const float4*)&w_hh[
                ((size_t)(g * HID + hg * 32 + lane)) * HID + w * 32 + q * 4];
            w2[g][q * 2 + 0] = pk(v.x, v.y);
            w2[g][q * 2 + 1] = pk(v.z, v.w);
        }
    // Input weights: same unit, i in [8w, 8w+8), i-paired f32x2
    unsigned long long wx[3][4];
#pragma unroll
    for (int g = 0; g < 3; g++)
#pragma unroll
        for (int q = 0; q < 4; q++) {
            const float2 v = *(const float2*)&w_ih[
                ((size_t)(g * HID + hg * 32 + lane)) * INP + w * 8 + q * 2];
            wx[g][q] = pk(v.x, v.y);
        }

    // Pointwise mapping (tid < 128): unit pj, batch pb
    const int pj = tid >> 2;
    const int pb = tid & 3;
    const int u  = hg * 32 + pj;
    const float bh_r  = b_ih[u] + b_hh[u];             // merged gate biases
    const float bh_z  = b_ih[HID + u] + b_hh[HID + u];
    const float bh_nx = b_ih[2 * HID + u];             // outside r
    const float bh_nh = b_hh[2 * HID + u];             // inside r
    const float fw    = fc_w[u];

    // x slice loader mapping: thread -> (batch tid>>6, input tid&63)
    const int xb = tid >> 6;
    const int xi = tid & 63;
    xsm[0][xb][xi] = x[((size_t)0 * BATCH + bg * 4 + xb) * INP + xi];

    float h_prev = 0.0f;
    __syncthreads();                       // weights + xsm[0] ready

    for (int t = 0; t < SEQ; t++) {
        const int cur = t & 1;

        unsigned long long acc[4][4];      // [gate r,z,nh,nx][b]
#pragma unroll
        for (int g = 0; g < 4; g++)
#pragma unroll
            for (int b = 0; b < 4; b++) acc[g][b] = 0ull;

        // x-projection MAC first (independent of mail; hidden in the wait)
#pragma unroll
        for (int b = 0; b < 4; b++) {
#pragma unroll
            for (int q = 0; q < 4; q++) {
                const unsigned long long xx =
                    *(const unsigned long long*)&xsm[cur][b][w * 8 + q * 2];
                fma2(acc[0][b], wx[0][q], xx);
                fma2(acc[1][b], wx[1][q], xx);
                fma2(acc[3][b], wx[2][q], xx);   // n-gate x part (slot 3)
            }
        }

        if (t > 0) {
            // Warp w polls ONLY producer w's mail (epoch t, parity (t-1)&1)
            const unsigned long long tt = (unsigned long long)t;
            const unsigned long long* mp = &d_hmail[
                ((size_t)(((t - 1) & 1) * BG + bg) * HG + w) * 128 + lane * 4];
            unsigned long long m0, m1, m2, m3;
            bool ok;
            do {
                asm volatile("ld.volatile.global.v2.u64 {%0,%1}, [%2];"
                             : "=l"(m0), "=l"(m1) : "l"(mp));
                asm volatile("ld.volatile.global.v2.u64 {%0,%1}, [%2];"
                             : "=l"(m2), "=l"(m3) : "l"(mp + 2));
                ok = __all_sync(0xFFFFFFFFu,
                                ((m0 >> 32) == tt) & ((m1 >> 32) == tt) &
                                ((m2 >> 32) == tt) & ((m3 >> 32) == tt));
            } while (!ok);
            hsm[w][0][lane] = __uint_as_float((unsigned)m0);
            hsm[w][1][lane] = __uint_as_float((unsigned)m1);
            hsm[w][2][lane] = __uint_as_float((unsigned)m2);
            hsm[w][3][lane] = __uint_as_float((unsigned)m3);
            __syncwarp();                  // warp-local staging only

            // Hidden MAC: 192 fma2, hsm loads broadcast within warp
#pragma unroll
            for (int b = 0; b < 4; b++) {
#pragma unroll
                for (int q = 0; q < 8; q++) {
                    const ulonglong2 hh = *(const ulonglong2*)&hsm[w][b][q * 4];
                    fma2(acc[0][b], w2[0][q * 2 + 0], hh.x);
                    fma2(acc[0][b], w2[0][q * 2 + 1], hh.y);
                    fma2(acc[1][b], w2[1][q * 2 + 0], hh.x);
                    fma2(acc[1][b], w2[1][q * 2 + 1], hh.y);
                    fma2(acc[2][b], w2[2][q * 2 + 0], hh.x);   // n hidden part
                    fma2(acc[2][b], w2[2][q * 2 + 1], hh.y);
                }
            }
        }

        // Per-warp partials: lane = unit, 4 batches packed per gate slot
#pragma unroll
        for (int g = 0; g < 4; g++) {
            const float2 a0 = unpk(acc[g][0]);
            const float2 a1 = unpk(acc[g][1]);
            const float2 a2 = unpk(acc[g][2]);
            const float2 a3 = unpk(acc[g][3]);
            float4 v = make_float4(a0.x + a0.y, a1.x + a1.y,
                                   a2.x + a2.y, a3.x + a3.y);
            *(float4*)&red[w][g][lane * 4] = v;
        }

        // Prefetch next step's x slice into the other xsm buffer
        if (t + 1 < SEQ)
            xsm[cur ^ 1][xb][xi] =
                x[((size_t)(t + 1) * BATCH + bg * 4 + xb) * INP + xi];
        __syncthreads();                   // partials + xsm ordering

        if (tid < 128) {
            float sr = 0.f, sz = 0.f, snh = 0.f, snx = 0.f;
            const int o = pj * 4 + pb;
#pragma unroll
            for (int ww = 0; ww < HG; ww++) {
                sr  += red[ww][0][o];
                sz  += red[ww][1][o];
                snh += red[ww][2][o];
                snx += red[ww][3][o];
            }
            // torch GRU: n = tanh(nx + b_ih_n + r*(nh + b_hh_n))
            const float rg_ = 1.0f / (1.0f + __expf(-(sr + bh_r)));
            const float zg_ = 1.0f / (1.0f + __expf(-(sz + bh_z)));
            const float ng_ = tanhf(snx + bh_nx + rg_ * (snh + bh_nh));
            const float hnew = fmaf(zg_, h_prev - ng_, ng_);
            h_prev = hnew;
            // Publish mail immediately: epoch t+1 | value, parity t&1
            const unsigned long long mail =
                ((unsigned long long)(t + 1) << 32) |
                (unsigned long long)__float_as_uint(hnew);
            unsigned long long* maddr = &d_hmail[
                ((size_t)(cur * BG + bg) * HG + hg) * 128 + pj * 4 + pb];
            asm volatile("st.relaxed.gpu.global.u64 [%0], %1;"
                         :: "l"(maddr), "l"(mail) : "memory");
            fcred[pb][pj] = fw * hnew;
        }
        __syncthreads();                   // fcred ready; red reusable

        if (tid < 4) {                     // fc partial (off critical path)
            float fs = 0.0f;
#pragma unroll
            for (int j = 0; j < 32; j++) fs += fcred[tid][j];
            d_fcp[((size_t)cc * SEQ + t) * 4 + tid] = fs;
        }
    }
}

// ---------------------------------------------------------------------------
// Kernel C: out[s][b] = fc_b + sum_hg fcp; re-zeroes mailbox for replay.
// ---------------------------------------------------------------------------
__global__ void __launch_bounds__(512) final_kernel(const float* __restrict__ fc_b,
                                                    float* __restrict__ out) {
    const int idx = blockIdx.x * 512 + threadIdx.x;
    if (idx < 2 * BG * HG * 32 * 4)                  // 32768 u64 mail words
        d_hmail[idx] = 0ull;
    if (idx >= SEQ * BATCH) return;
    const int s  = idx >> 6;
    const int b6 = idx & 63;
    const int bg = b6 >> 2;
    const int bl = b6 & 3;
    float sum = fc_b[0];
#pragma unroll
    for (int hg = 0; hg < HG; hg++)
        sum += d_fcp[((size_t)(bg * HG + hg) * SEQ + s) * 4 + bl];
    out[idx] = sum;
}

extern "C" void kernel_launch(void* const* d_in, const int* in_sizes, int n_in,
                              void* d_out, int out_size) {
    const float* x    = (const float*)d_in[0];
    const float* w_ih = (const float*)d_in[1];
    const float* w_hh = (const float*)d_in[2];
    const float* b_ih = (const float*)d_in[3];
    const float* b_hh = (const float*)d_in[4];
    const float* fc_w = (const float*)d_in[5];
    const float* fc_b = (const float*)d_in[6];
    float* out = (float*)d_out;

    scan_kernel<<<NCTA, 256>>>(x, w_ih, w_hh, b_ih, b_hh, fc_w);  // fused scan
    final_kernel<<<(SEQ * BATCH + 511) / 512, 512>>>(fc_b, out);
}

// round 15
// speedup vs baseline: 1.6417x; 1.1079x over previous
#include <cuda_runtime.h>
#include <cstdint>

#define SEQ   4096
#define BATCH 64
#define INP   64
#define HID   256
#define G3    768
#define BG    16          // batch columns (4 batches each)
#define HG    8           // hidden groups (32 units each) = warps/CTA
#define NCTA  (BG*HG)     // 128 scan CTAs, occupancy 1

// Scratch (static device allocations are the sanctioned workaround)
__device__ float d_xg[(size_t)SEQ * G3 * BATCH];             // [s][g][b]
__device__ unsigned long long d_hmail[2 * BG * HG * 32 * 4]; // [par][bg][p][j][b]
__device__ float d_fcp[(size_t)NCTA * SEQ * 4];              // [bg*8+hg][t][b4]

__device__ __forceinline__ void fma2(unsigned long long& acc,
                                     unsigned long long a,
                                     unsigned long long b) {
    asm("fma.rn.f32x2 %0, %1, %2, %0;" : "+l"(acc) : "l"(a), "l"(b));
}
__device__ __forceinline__ unsigned long long pk(float a, float b) {
    unsigned long long r;
    asm("mov.b64 %0, {%1, %2};" : "=l"(r) : "f"(a), "f"(b));
    return r;
}
__device__ __forceinline__ float2 unpk(unsigned long long v) {
    float lo, hi;
    asm("mov.b64 {%0, %1}, %2;" : "=f"(lo), "=f"(hi) : "l"(v));
    return make_float2(lo, hi);
}
__device__ __forceinline__ float tanh_fast(float x) {
    float r;
    asm("tanh.approx.f32 %0, %1;" : "=f"(r) : "f"(x));
    return r;
}
__device__ __forceinline__ float sigmoid_fast(float x) {
    return fmaf(tanh_fast(0.5f * x), 0.5f, 0.5f);
}

// ---------------------------------------------------------------------------
// Kernel A: xg[s][g][b] = sum_i x[s][b][i] * w_ih[g][i] + b_ih[g]
// ---------------------------------------------------------------------------
__global__ void __launch_bounds__(256) xg_kernel(const float* __restrict__ x,
                                                 const float* __restrict__ w_ih,
                                                 const float* __restrict__ b_ih) {
    __shared__ float xs[INP][BATCH + 1];
    __shared__ float ws[64][INP];
    const int s   = blockIdx.x;
    const int g0  = blockIdx.y * 64;
    const int tid = threadIdx.x;

    const float* xsrc = x + (size_t)s * BATCH * INP;
    for (int idx = tid; idx < BATCH * INP; idx += 256) {
        int b = idx >> 6, i = idx & 63;
        xs[i][b] = xsrc[idx];
    }
    const float* wsrc = w_ih + (size_t)g0 * INP;
    for (int idx = tid; idx < 64 * INP; idx += 256)
        ws[idx >> 6][idx & 63] = wsrc[idx];
    __syncthreads();

    const int b  = tid & 63;
    const int gg = tid >> 6;
    float xr[INP];
#pragma unroll
    for (int i = 0; i < INP; i++) xr[i] = xs[i][b];

    float acc[16];
#pragma unroll
    for (int u = 0; u < 16; u++) acc[u] = 0.0f;
    const int gb = gg * 16;
#pragma unroll
    for (int i4 = 0; i4 < INP / 4; i4++) {
#pragma unroll
        for (int u = 0; u < 16; u++) {
            float4 w4 = *(const float4*)&ws[gb + u][i4 * 4];
            acc[u] += w4.x * xr[i4 * 4 + 0];
            acc[u] += w4.y * xr[i4 * 4 + 1];
            acc[u] += w4.z * xr[i4 * 4 + 2];
            acc[u] += w4.w * xr[i4 * 4 + 3];
        }
    }
    float* dst = d_xg + ((size_t)s * G3 + g0) * BATCH;
#pragma unroll
    for (int u = 0; u < 16; u++) {
        int gl = gb + u;
        __stcs(&dst[(size_t)gl * BATCH + b], acc[u] + b_ih[g0 + gl]);
    }
}

// ---------------------------------------------------------------------------
// Kernel B: persistent GRU scan, warp-per-producer ready-order consumption
// (the 6.58ms R8 structure), SINGLE CHANGE: tanh.approx activations to
// shorten the pointwise latency on the serial critical path.
// ---------------------------------------------------------------------------
__global__ void __launch_bounds__(256, 1) scan_kernel(const float* __restrict__ w_hh,
                                                      const float* __restrict__ b_hh,
                                                      const float* __restrict__ fc_w) {
    __shared__ float hsm[HG][4][32];       // [warp][b_local][k_local]
    __shared__ float red[HG][3][128];      // [warp][gate][j*4+b]
    __shared__ float fcred[4][32];         // [b_local][j]

    const int c    = blockIdx.x;
    const int bg   = c & (BG - 1);
    const int hg   = c >> 4;
    const int tid  = threadIdx.x;
    const int w    = tid >> 5;             // warp = producer index = k strip
    const int lane = tid & 31;

    // Weights: unit u = hg*32+lane, k in [w*32, w*32+32), k-paired as float2
    unsigned long long w2[3][16];
#pragma unroll
    for (int g = 0; g < 3; g++)
#pragma unroll
        for (int q = 0; q < 8; q++) {
            const float4 v = *(const float4*)&w_hh[
                ((size_t)(g * HID + hg * 32 + lane)) * HID + w * 32 + q * 4];
            w2[g][q * 2 + 0] = pk(v.x, v.y);
            w2[g][q * 2 + 1] = pk(v.z, v.w);
        }

    // Pointwise mapping (tid < 128): unit pj, batch pb
    const int pj = tid >> 2;
    const int pb = tid & 3;
    const int u  = hg * 32 + pj;
    const float bh_r = b_hh[u];
    const float bh_z = b_hh[HID + u];
    const float bh_n = b_hh[2 * HID + u];
    const float fw   = fc_w[u];

    float h_prev = 0.0f;
    __syncthreads();

    for (int t = 0; t < SEQ; t++) {
        // Prefetch input-side gates (overlaps poll + MAC)
        float xrv = 0.f, xzv = 0.f, xnv = 0.f;
        if (tid < 128) {
            const size_t base = ((size_t)t * G3 + u) * BATCH + (bg * 4 + pb);
            xrv = __ldcs(&d_xg[base]);
            xzv = __ldcs(&d_xg[base + (size_t)HID * BATCH]);
            xnv = __ldcs(&d_xg[base + (size_t)2 * HID * BATCH]);
        }

        unsigned long long acc[3][4];      // [gate][b], f32x2 over (k0,k1)
#pragma unroll
        for (int g = 0; g < 3; g++)
#pragma unroll
            for (int b = 0; b < 4; b++) acc[g][b] = 0ull;

        if (t > 0) {
            // Warp w polls ONLY producer w's mail (epoch t, parity (t-1)&1)
            const unsigned long long tt = (unsigned long long)t;
            const unsigned long long* mp = &d_hmail[
                ((size_t)(((t - 1) & 1) * BG + bg) * HG + w) * 128 + lane * 4];
            unsigned long long m0, m1, m2, m3;
            bool ok;
            do {
                asm volatile("ld.volatile.global.v2.u64 {%0,%1}, [%2];"
                             : "=l"(m0), "=l"(m1) : "l"(mp));
                asm volatile("ld.volatile.global.v2.u64 {%0,%1}, [%2];"
                             : "=l"(m2), "=l"(m3) : "l"(mp + 2));
                ok = __all_sync(0xFFFFFFFFu,
                                ((m0 >> 32) == tt) & ((m1 >> 32) == tt) &
                                ((m2 >> 32) == tt) & ((m3 >> 32) == tt));
            } while (!ok);
            hsm[w][0][lane] = __uint_as_float((unsigned)m0);
            hsm[w][1][lane] = __uint_as_float((unsigned)m1);
            hsm[w][2][lane] = __uint_as_float((unsigned)m2);
            hsm[w][3][lane] = __uint_as_float((unsigned)m3);
            __syncwarp();                  // warp-local staging only

            // Strip MAC: 192 fma2, hsm loads broadcast (same addr all lanes)
#pragma unroll
            for (int b = 0; b < 4; b++) {
#pragma unroll
                for (int q = 0; q < 8; q++) {
                    const ulonglong2 hh = *(const ulonglong2*)&hsm[w][b][q * 4];
#pragma unroll
                    for (int g = 0; g < 3; g++) {
                        fma2(acc[g][b], w2[g][q * 2 + 0], hh.x);
                        fma2(acc[g][b], w2[g][q * 2 + 1], hh.y);
                    }
                }
            }
        }

        // Store per-warp partials: lane = unit, pack 4 batches per gate
#pragma unroll
        for (int g = 0; g < 3; g++) {
            const float2 a0 = unpk(acc[g][0]);
            const float2 a1 = unpk(acc[g][1]);
            const float2 a2 = unpk(acc[g][2]);
            const float2 a3 = unpk(acc[g][3]);
            float4 v = make_float4(a0.x + a0.y, a1.x + a1.y,
                                   a2.x + a2.y, a3.x + a3.y);
            *(float4*)&red[w][g][lane * 4] = v;
        }
        __syncthreads();                   // all warps' partials visible

        if (tid < 128) {
            float sr = 0.f, sz = 0.f, sn = 0.f;
            const int o = pj * 4 + pb;
#pragma unroll
            for (int ww = 0; ww < HG; ww++) {
                sr += red[ww][0][o];
                sz += red[ww][1][o];
                sn += red[ww][2][o];
            }
            // torch GRU: n = tanh(xn + r*(hn + bhh_n)), HW-approx activations
            const float rg_ = sigmoid_fast(xrv + sr + bh_r);
            const float zg_ = sigmoid_fast(xzv + sz + bh_z);
            const float ng_ = tanh_fast(xnv + rg_ * (sn + bh_n));
            const float hnew = fmaf(zg_, h_prev - ng_, ng_);
            h_prev = hnew;
            // Publish mail immediately: epoch t+1 | value, parity t&1
            const unsigned long long mail =
                ((unsigned long long)(t + 1) << 32) |
                (unsigned long long)__float_as_uint(hnew);
            unsigned long long* maddr = &d_hmail[
                ((size_t)((t & 1) * BG + bg) * HG + hg) * 128 + pj * 4 + pb];
            asm volatile("st.relaxed.gpu.global.u64 [%0], %1;"
                         :: "l"(maddr), "l"(mail) : "memory");
            fcred[pb][pj] = fw * hnew;
        }
        __syncthreads();                   // fcred ready; red reusable

        if (tid < 4) {                     // fc partial (off critical path)
            float fs = 0.0f;
#pragma unroll
            for (int j = 0; j < 32; j++) fs += fcred[tid][j];
            d_fcp[((size_t)(bg * HG + hg) * SEQ + t) * 4 + tid] = fs;
        }
    }
}

// ---------------------------------------------------------------------------
// Kernel C: out[s][b] = fc_b + sum_hg fcp; re-zeroes the mailbox for replay.
// ---------------------------------------------------------------------------
__global__ void __launch_bounds__(512) final_kernel(const float* __restrict__ fc_b,
                                                    float* __restrict__ out) {
    const int idx = blockIdx.x * 512 + threadIdx.x;
    if (idx < 2 * BG * HG * 32 * 4)                  // 32768 u64 mail words
        d_hmail[idx] = 0ull;
    if (idx >= SEQ * BATCH) return;
    const int s  = idx >> 6;
    const int b6 = idx & 63;
    const int bg = b6 >> 2;
    const int bl = b6 & 3;
    float sum = fc_b[0];
#pragma unroll
    for (int hg = 0; hg < HG; hg++)
        sum += d_fcp[((size_t)(bg * HG + hg) * SEQ + s) * 4 + bl];
    out[idx] = sum;
}

extern "C" void kernel_launch(void* const* d_in, const int* in_sizes, int n_in,
                              void* d_out, int out_size) {
    const float* x    = (const float*)d_in[0];
    const float* w_ih = (const float*)d_in[1];
    const float* w_hh = (const float*)d_in[2];
    const float* b_ih = (const float*)d_in[3];
    const float* b_hh = (const float*)d_in[4];
    const float* fc_w = (const float*)d_in[5];
    const float* fc_b = (const float*)d_in[6];
    float* out = (float*)d_out;

    dim3 ga(SEQ, G3 / 64);
    xg_kernel<<<ga, 256>>>(x, w_ih, b_ih);                 // input projections
    scan_kernel<<<NCTA, 256>>>(w_hh, b_hh, fc_w);          // ready-order scan
    final_kernel<<<(SEQ * BATCH + 511) / 512, 512>>>(fc_b, out);
}